// round 14
// baseline (speedup 1.0000x reference)
#include <cuda_runtime.h>
#include <cuda_fp16.h>
#include <cstdint>
#include <math.h>

#define B_    2
#define S_    2048
#define HID   1024
#define NH    16
#define NKV   4
#define HD    64
#define NCAT  1536            // 1024 (Q) + 256 (K) + 256 (V)

// ---------------------------------------------------------------------------
// Scratch (device globals)
// ---------------------------------------------------------------------------
__device__ float g_cos[S_ * 32];
__device__ float g_sin[S_ * 32];
__device__ float g_bias[NCAT];

__device__ __half g_hs[(size_t)B_ * S_ * HID];
__device__ __half g_at[(size_t)B_ * S_ * HID];
__device__ __half g_Wc[NCAT * HID];                  // [1536,1024] K-major rows
__device__ __half g_Wo[HID * HID];
__device__ __half g_Q[(size_t)B_ * S_ * HID];        // post-rope Q fp16 (pre-scaled)
__device__ __half g_K[(size_t)B_ * S_ * NKV * HD];   // post-rope K fp16
__device__ __half g_Vt[(size_t)B_ * NKV * HD * S_];  // [b,kvh,d,s] fp16

// ---------------------------------------------------------------------------
// helpers
// ---------------------------------------------------------------------------
__device__ __forceinline__ uint32_t smem_u32(const void* p) {
    uint32_t a;
    asm("{ .reg .u64 t; cvta.to.shared.u64 t, %1; cvt.u32.u64 %0, t; }" : "=r"(a) : "l"(p));
    return a;
}
#define LDSM_X4(r0, r1, r2, r3, addr) \
    asm volatile("ldmatrix.sync.aligned.m8n8.x4.shared.b16 {%0,%1,%2,%3}, [%4];" \
        : "=r"(r0), "=r"(r1), "=r"(r2), "=r"(r3) : "r"(addr))
#define CP_A16(dst, src) \
    asm volatile("cp.async.cg.shared.global [%0], [%1], 16;" :: "r"(dst), "l"(src))
#define CP_COMMIT() asm volatile("cp.async.commit_group;" ::: "memory")
#define CP_WAIT0()  asm volatile("cp.async.wait_group 0;" ::: "memory")
#define CP_WAIT1()  asm volatile("cp.async.wait_group 1;" ::: "memory")

__device__ __forceinline__ void mma_f16(float* d, const uint32_t* a,
                                        uint32_t b0, uint32_t b1) {
    asm volatile(
        "mma.sync.aligned.m16n8k16.row.col.f32.f16.f16.f32 "
        "{%0,%1,%2,%3}, {%4,%5,%6,%7}, {%8,%9}, {%0,%1,%2,%3};"
        : "+f"(d[0]), "+f"(d[1]), "+f"(d[2]), "+f"(d[3])
        : "r"(a[0]), "r"(a[1]), "r"(a[2]), "r"(a[3]), "r"(b0), "r"(b1));
}
__device__ __forceinline__ uint32_t pack2h(float x, float y) {
    __half2 h = __floats2half2_rn(x, y);
    return *reinterpret_cast<uint32_t*>(&h);
}
__device__ __forceinline__ float fexp2(float x) {
    float y;
    asm("ex2.approx.f32 %0, %1;" : "=f"(y) : "f"(x));
    return y;
}
__device__ __forceinline__ uint32_t hexp2x2(uint32_t x) {
    uint32_t y;
    asm("ex2.approx.f16x2 %0, %1;" : "=r"(y) : "r"(x));
    return y;
}

// ---------------------------------------------------------------------------
// Prep: z=0..3 weight transpose to [N,K] fp16; z=4 rope table + bias concat.
// ---------------------------------------------------------------------------
__global__ void prep_kernel(const float* __restrict__ Wq,
                            const float* __restrict__ Wk,
                            const float* __restrict__ Wv,
                            const float* __restrict__ Wo,
                            const float* __restrict__ bq,
                            const float* __restrict__ bk,
                            const float* __restrict__ bv) {
    int z = blockIdx.z;
    int tid = threadIdx.y * 32 + threadIdx.x;
    if (z == 4) {
        int idx = (blockIdx.y * 32 + blockIdx.x) * 256 + tid;
        if (idx < NCAT)
            g_bias[idx] = (idx < 1024) ? bq[idx] : (idx < 1280) ? bk[idx - 1024] : bv[idx - 1280];
        if (idx >= S_ * 32) return;
        int t = idx >> 5, j = idx & 31;
        double inv = exp2(-(double)j * 0.5190512648261507);
        float ang = (float)((double)t * inv);
        float s, c;
        sincosf(ang, &s, &c);
        g_cos[idx] = c;
        g_sin[idx] = s;
        return;
    }

    __shared__ float t[32][33];
    const float* W;
    __half* dst;
    int N, rowoff;
    if (z == 0)      { W = Wq; N = HID; rowoff = 0;    dst = g_Wc; }
    else if (z == 1) { W = Wk; N = 256; rowoff = 1024; dst = g_Wc; }
    else if (z == 2) { W = Wv; N = 256; rowoff = 1280; dst = g_Wc; }
    else             { W = Wo; N = HID; rowoff = 0;    dst = g_Wo; }

    int n0 = blockIdx.x * 32, k0 = blockIdx.y * 32;
    if (n0 >= N) return;
    int x = threadIdx.x, y = threadIdx.y;
    #pragma unroll
    for (int yy = y; yy < 32; yy += 8)
        t[yy][x] = W[(size_t)(k0 + yy) * N + n0 + x];
    __syncthreads();
    #pragma unroll
    for (int yy = y; yy < 32; yy += 8)
        dst[(size_t)(rowoff + n0 + yy) * HID + k0 + x] = __float2half(t[x][yy]);
}

__global__ void cvt_kernel(const float* __restrict__ in, __half* __restrict__ o, int n) {
    int i = (blockIdx.x * blockDim.x + threadIdx.x) * 2;
    if (i >= n) return;
    float2 v = *reinterpret_cast<const float2*>(in + i);
    *reinterpret_cast<uint32_t*>(o + i) = pack2h(v.x, v.y);
}

// ---------------------------------------------------------------------------
// GEMM fp16 mma.sync: BK=64 chunks, 3-stage ring, ONE sync per chunk.
// MODE 0: fp32 C + bias. MODE 1: fused RoPE (Q pre-scaled) + V transpose.
// ---------------------------------------------------------------------------
#define GEMM_SMEM (3 * 32768)

template <int MODE>
__global__ __launch_bounds__(256, 2) void gemm_mma_kernel(
    const __half* __restrict__ Ap, const __half* __restrict__ Wp,
    const float* __restrict__ bias, float* __restrict__ C, int ldc, int K)
{
    extern __shared__ char smx[];
    const int tid = threadIdx.x, lane = tid & 31, wid = tid >> 5;
    const int wm = wid & 1, wn = wid >> 1;
    const int m0 = blockIdx.y * 128, n0 = blockIdx.x * 128;
    const uint32_t sbase = smem_u32(smx);

    float acc[4][4][4];
    #pragma unroll
    for (int a = 0; a < 4; a++)
        #pragma unroll
        for (int bb = 0; bb < 4; bb++)
            #pragma unroll
            for (int c = 0; c < 4; c++) acc[a][bb][c] = 0.f;

    auto load_stage = [&](int ch, int st) {
        const uint32_t base = sbase + (uint32_t)st * 32768u;
        const int k0 = ch * 64;
        #pragma unroll
        for (int it = 0; it < 8; ++it) {
            int i = it * 256 + tid;
            int mat = i >> 10;
            int row = (i >> 3) & 127;
            int seg = i & 7;
            uint32_t dst = base + (uint32_t)mat * 16384u
                         + (uint32_t)(row * 128 + (((seg ^ (row & 7))) << 4));
            const __half* p = mat ? (Wp + (size_t)(n0 + row) * K)
                                  : (Ap + (size_t)(m0 + row) * K);
            CP_A16(dst, p + k0 + seg * 8);
        }
    };

    const int NCH = K / 64;
    load_stage(0, 0); CP_COMMIT();
    if (NCH > 1) { load_stage(1, 1); CP_COMMIT(); }

    int stc = 0;
    for (int ch = 0; ch < NCH; ++ch) {
        if (ch + 1 < NCH) CP_WAIT1(); else CP_WAIT0();
        __syncthreads();

        const uint32_t sA = sbase + (uint32_t)stc * 32768u;
        const uint32_t sW = sA + 16384u;

        #pragma unroll
        for (int ks = 0; ks < 4; ++ks) {
            const int colh = ks * 2 + (lane >> 4);
            uint32_t a[4][4], bfr[2][4];
            #pragma unroll
            for (int mi = 0; mi < 4; ++mi) {
                int row = wm * 64 + mi * 16 + (lane & 15);
                LDSM_X4(a[mi][0], a[mi][1], a[mi][2], a[mi][3],
                        sA + (uint32_t)(row * 128 + ((colh ^ (row & 7)) << 4)));
            }
            #pragma unroll
            for (int g = 0; g < 2; ++g) {
                int row = wn * 32 + g * 16 + (lane & 15);
                LDSM_X4(bfr[g][0], bfr[g][1], bfr[g][2], bfr[g][3],
                        sW + (uint32_t)(row * 128 + ((colh ^ (row & 7)) << 4)));
            }
            #pragma unroll
            for (int mi = 0; mi < 4; ++mi) {
                #pragma unroll
                for (int j = 0; j < 4; ++j) {
                    const int g = j >> 1, p = j & 1;
                    mma_f16(acc[mi][j], a[mi], bfr[g][p], bfr[g][p + 2]);
                }
            }
            if (ks == 0 && ch + 2 < NCH) { load_stage(ch + 2, (stc + 2) % 3); CP_COMMIT(); }
        }
        stc = (stc == 2) ? 0 : stc + 1;
    }

    // epilogue
    const float SC2 = 0.125f * 1.44269504f;    // folded into Q only
    #pragma unroll
    for (int mi = 0; mi < 4; ++mi) {
        const int r = m0 + wm * 64 + mi * 16 + (lane >> 2);
        #pragma unroll
        for (int j = 0; j < 4; ++j) {
            const int col = n0 + wn * 32 + j * 8 + (lane & 3) * 2;
            const float b0 = bias[col], b1 = bias[col + 1];
            float x0 = acc[mi][j][0] + b0, x1 = acc[mi][j][1] + b1;
            float x2 = acc[mi][j][2] + b0, x3 = acc[mi][j][3] + b1;
            if (MODE == 0) {
                *reinterpret_cast<float2*>(C + (size_t)r * ldc + col) = make_float2(x0, x1);
                *reinterpret_cast<float2*>(C + (size_t)(r + 8) * ldc + col) = make_float2(x2, x3);
            } else {
                if (col < 1280) {
                    const int pos0 = r & (S_ - 1), pos1 = (r + 8) & (S_ - 1);
                    const int j0 = col & 31;
                    float2 cc0 = *reinterpret_cast<const float2*>(&g_cos[pos0 * 32 + j0]);
                    float2 ss0 = *reinterpret_cast<const float2*>(&g_sin[pos0 * 32 + j0]);
                    float2 cc1 = *reinterpret_cast<const float2*>(&g_cos[pos1 * 32 + j0]);
                    float2 ss1 = *reinterpret_cast<const float2*>(&g_sin[pos1 * 32 + j0]);
                    float y0 = x0 * cc0.x - x1 * ss0.x;
                    float y1 = x1 * cc0.y + x0 * ss0.y;
                    float y2 = x2 * cc1.x - x3 * ss1.x;
                    float y3 = x3 * cc1.y + x2 * ss1.y;
                    if (col < 1024) {
                        y0 *= SC2; y1 *= SC2; y2 *= SC2; y3 *= SC2;
                        uint32_t* o = reinterpret_cast<uint32_t*>(g_Q);
                        o[(size_t)r * 512 + (col >> 1)]       = pack2h(y0, y1);
                        o[(size_t)(r + 8) * 512 + (col >> 1)] = pack2h(y2, y3);
                    } else {
                        uint32_t* o = reinterpret_cast<uint32_t*>(g_K);
                        o[(size_t)r * 128 + ((col - 1024) >> 1)]       = pack2h(y0, y1);
                        o[(size_t)(r + 8) * 128 + ((col - 1024) >> 1)] = pack2h(y2, y3);
                    }
                } else {
                    // fused V transpose: fp16 to g_Vt[b][kvh][d][s]
                    const int d = col - 1280;
                    const int kvh = d >> 6, dd = d & 63;
                    const int bb2 = r >> 11, s = r & (S_ - 1);
                    __half* vt = g_Vt + ((size_t)(bb2 * NKV + kvh) * HD + dd) * S_;
                    vt[s]           = __float2half(x0);
                    vt[S_ + s]      = __float2half(x1);
                    vt[s + 8]       = __float2half(x2);
                    vt[S_ + s + 8]  = __float2half(x3);
                }
            }
        }
    }
}

// ---------------------------------------------------------------------------
// Flash attention fp16: 4 warps x 32 query rows (128 threads) -> halved LDSM
// traffic. Load-balanced pairs {15-p, p}, 3-stage K/V ring, ONE sync/tile,
// ex2.f16x2 softmax, ones-MMA row sums, warp-ballot skip-rescale.
// ---------------------------------------------------------------------------
#define AQ_OFF  0                                  // 128 x 144 = 18432
#define AST_OFF 18432                              // 3 stages x (K 9216 + V 9216)
#define AOK_OFF (AST_OFF + 3 * 18432)              // 32 tile-ok flags
#define AAM_OFF (AOK_OFF + 128)                    // mask 8192
#define ATTN_SMEM (AAM_OFF + S_ * 4)

__global__ __launch_bounds__(128, 2) void attn_mma_kernel(
    const int* __restrict__ amask, __half* __restrict__ atout)
{
    extern __shared__ char sm[];
    const uint32_t sb = smem_u32(sm);
    int* am  = reinterpret_cast<int*>(sm + AAM_OFF);
    int* amok = reinterpret_cast<int*>(sm + AOK_OFF);

    const int tid = threadIdx.x, lane = tid & 31, w = tid >> 5;   // w = 0..3
    const int pr = blockIdx.x, h = blockIdx.y, b = blockIdx.z;
    const int kvh = h >> 2;
    const uint32_t ONES = 0x3C003C00u;

    #pragma unroll
    for (int it = 0; it < 16; ++it)
        am[it * 128 + tid] = amask[b * S_ + it * 128 + tid];
    __syncthreads();
    if (tid < 32) {
        int ok = 1;
        for (int j = 0; j < 64; ++j) ok &= (am[tid * 64 + j] != 0);
        amok[tid] = ok;
    }

    auto prefetch_kv = [&](int kt, int st) {
        const int k0 = kt * 64;
        const uint32_t base = sb + AST_OFF + (uint32_t)st * 18432u;
        if (tid < 64) {
            const __half* kp = g_K + (size_t)(b * S_ + k0 + tid) * (NKV * HD) + kvh * HD;
            uint32_t dst = base + (uint32_t)tid * 144u;
            #pragma unroll
            for (int j = 0; j < 8; ++j)
                CP_A16(dst + j * 16, kp + j * 8);
        } else {
            const int row = tid - 64;   // d index
            const __half* vp = g_Vt + ((size_t)(b * NKV + kvh) * HD + row) * S_ + k0;
            uint32_t dst = base + 9216u + (uint32_t)row * 144u;
            #pragma unroll
            for (int j = 0; j < 8; ++j)
                CP_A16(dst + j * 16, vp + j * 8);
        }
    };

    for (int half = 0; half < 2; ++half) {
        const int qb = half ? pr : (15 - pr);      // long block first
        const int q0 = qb * 128;
        const int nkt = 2 * qb + 2;                // >= 2

        // Q tile: row = tid, 8 segs
        {
            const __half* qp = g_Q + (size_t)(b * S_ + q0 + tid) * HID + h * HD;
            uint32_t dst = sb + AQ_OFF + (uint32_t)tid * 144u;
            #pragma unroll
            for (int j = 0; j < 8; ++j)
                CP_A16(dst + j * 16, qp + j * 8);
        }
        prefetch_kv(0, 0); CP_COMMIT();            // group0 = Q + kv0
        prefetch_kv(1, 1); CP_COMMIT();            // group1 = kv1

        CP_WAIT1();
        __syncthreads();

        // preload Q fragments: 2 row-groups x 4 ks
        uint32_t qf[2][4][4];
        #pragma unroll
        for (int rg = 0; rg < 2; ++rg) {
            uint32_t rb = sb + AQ_OFF + (uint32_t)(w * 32 + rg * 16 + (lane & 15)) * 144;
            #pragma unroll
            for (int ks = 0; ks < 4; ++ks)
                LDSM_X4(qf[rg][ks][0], qf[rg][ks][1], qf[rg][ks][2], qf[rg][ks][3],
                        rb + (uint32_t)(ks * 32 + ((lane >> 4) << 4)));
        }

        float acc[2][8][4];
        #pragma unroll
        for (int rg = 0; rg < 2; ++rg)
            #pragma unroll
            for (int nt = 0; nt < 8; ++nt)
                #pragma unroll
                for (int c = 0; c < 4; ++c) acc[rg][nt][c] = 0.f;
        float mrun[2][2] = {{-1e30f, -1e30f}, {-1e30f, -1e30f}};
        float lrun[2][2] = {{0.f, 0.f}, {0.f, 0.f}};
        int rowg[2][2];
        #pragma unroll
        for (int rg = 0; rg < 2; ++rg) {
            rowg[rg][0] = q0 + w * 32 + rg * 16 + (lane >> 2);
            rowg[rg][1] = rowg[rg][0] + 8;
        }

        int stc = 0;
        for (int kt = 0; kt < nkt; ++kt) {
            if (kt > 0) {
                if (kt + 1 < nkt) CP_WAIT1(); else CP_WAIT0();
                __syncthreads();
            }
            if (kt + 2 < nkt) { prefetch_kv(kt + 2, (stc + 2) % 3); CP_COMMIT(); }

            const int k0 = kt * 64;
            const uint32_t stage = sb + AST_OFF + (uint32_t)stc * 18432u;

            // ---- S = Q K^T for 32 rows ----
            float s[2][8][4];
            #pragma unroll
            for (int rg = 0; rg < 2; ++rg)
                #pragma unroll
                for (int nt = 0; nt < 8; ++nt)
                    #pragma unroll
                    for (int c = 0; c < 4; ++c) s[rg][nt][c] = 0.f;

            #pragma unroll
            for (int ks = 0; ks < 4; ++ks) {
                const uint32_t coff = (uint32_t)(ks * 32 + ((lane >> 4) << 4));
                uint32_t kf[4][4];
                #pragma unroll
                for (int g = 0; g < 4; ++g)
                    LDSM_X4(kf[g][0], kf[g][1], kf[g][2], kf[g][3],
                            stage + (uint32_t)(g * 16 + (lane & 15)) * 144 + coff);
                #pragma unroll
                for (int rg = 0; rg < 2; ++rg)
                    #pragma unroll
                    for (int g = 0; g < 4; ++g)
                        #pragma unroll
                        for (int p = 0; p < 2; ++p)
                            mma_f16(s[rg][g * 2 + p], qf[rg][ks], kf[g][p], kf[g][p + 2]);
            }

            // ---- masking (fast-path skips everything) ----
            const bool fast = (k0 + 63 <= q0 + w * 32) && amok[k0 >> 6];
            if (!fast) {
                #pragma unroll
                for (int rg = 0; rg < 2; ++rg)
                    #pragma unroll
                    for (int nt = 0; nt < 8; ++nt) {
                        int cl = nt * 8 + (lane & 3) * 2;
                        int cg0 = k0 + cl, cg1 = cg0 + 1;
                        bool ok0 = am[cg0] != 0, ok1 = am[cg1] != 0;
                        if (!(ok0 && cg0 <= rowg[rg][0])) s[rg][nt][0] = -1e30f;
                        if (!(ok1 && cg1 <= rowg[rg][0])) s[rg][nt][1] = -1e30f;
                        if (!(ok0 && cg0 <= rowg[rg][1])) s[rg][nt][2] = -1e30f;
                        if (!(ok1 && cg1 <= rowg[rg][1])) s[rg][nt][3] = -1e30f;
                    }
            }

            // ---- online softmax ----
            float mt[2][2] = {{-1e30f, -1e30f}, {-1e30f, -1e30f}};
            #pragma unroll
            for (int rg = 0; rg < 2; ++rg)
                #pragma unroll
                for (int nt = 0; nt < 8; ++nt) {
                    mt[rg][0] = fmaxf(mt[rg][0], fmaxf(s[rg][nt][0], s[rg][nt][1]));
                    mt[rg][1] = fmaxf(mt[rg][1], fmaxf(s[rg][nt][2], s[rg][nt][3]));
                }
            #pragma unroll
            for (int rg = 0; rg < 2; ++rg)
                #pragma unroll
                for (int c = 0; c < 2; ++c) {
                    mt[rg][c] = fmaxf(mt[rg][c], __shfl_xor_sync(0xffffffffu, mt[rg][c], 1));
                    mt[rg][c] = fmaxf(mt[rg][c], __shfl_xor_sync(0xffffffffu, mt[rg][c], 2));
                }

            float mn[2][2];
            bool changed = false;
            #pragma unroll
            for (int rg = 0; rg < 2; ++rg)
                #pragma unroll
                for (int c = 0; c < 2; ++c) {
                    mn[rg][c] = fmaxf(mrun[rg][c], mt[rg][c]);
                    changed |= (mn[rg][c] > mrun[rg][c]);
                }

            // P = exp2(s - mn) packed fp16
            uint32_t pa[2][4][4];
            #pragma unroll
            for (int rg = 0; rg < 2; ++rg)
                #pragma unroll
                for (int nt = 0; nt < 8; ++nt) {
                    int t = nt >> 1, q = nt & 1;
                    pa[rg][t][q * 2 + 0] = hexp2x2(pack2h(s[rg][nt][0] - mn[rg][0],
                                                          s[rg][nt][1] - mn[rg][0]));
                    pa[rg][t][q * 2 + 1] = hexp2x2(pack2h(s[rg][nt][2] - mn[rg][1],
                                                          s[rg][nt][3] - mn[rg][1]));
                }

            // row sums via ones-MMA
            float sum4[2][4];
            #pragma unroll
            for (int rg = 0; rg < 2; ++rg) {
                sum4[rg][0] = sum4[rg][1] = sum4[rg][2] = sum4[rg][3] = 0.f;
                #pragma unroll
                for (int ks = 0; ks < 4; ++ks)
                    mma_f16(sum4[rg], pa[rg][ks], ONES, ONES);
            }

            // rescale only if any row's max changed (warp vote)
            if (__ballot_sync(0xffffffffu, changed)) {
                float corr[2][2];
                #pragma unroll
                for (int rg = 0; rg < 2; ++rg)
                    #pragma unroll
                    for (int c = 0; c < 2; ++c)
                        corr[rg][c] = fexp2(mrun[rg][c] - mn[rg][c]);
                #pragma unroll
                for (int rg = 0; rg < 2; ++rg) {
                    lrun[rg][0] = lrun[rg][0] * corr[rg][0] + sum4[rg][0];
                    lrun[rg][1] = lrun[rg][1] * corr[rg][1] + sum4[rg][2];
                    mrun[rg][0] = mn[rg][0];
                    mrun[rg][1] = mn[rg][1];
                    #pragma unroll
                    for (int nt = 0; nt < 8; ++nt) {
                        acc[rg][nt][0] *= corr[rg][0]; acc[rg][nt][1] *= corr[rg][0];
                        acc[rg][nt][2] *= corr[rg][1]; acc[rg][nt][3] *= corr[rg][1];
                    }
                }
            } else {
                #pragma unroll
                for (int rg = 0; rg < 2; ++rg) {
                    lrun[rg][0] += sum4[rg][0];
                    lrun[rg][1] += sum4[rg][2];
                }
            }

            // ---- O += P V ----
            const uint32_t vstage = stage + 9216u;
            #pragma unroll
            for (int ks = 0; ks < 4; ++ks) {
                const uint32_t coff = (uint32_t)(ks * 32 + ((lane >> 4) << 4));
                uint32_t vf[4][4];
                #pragma unroll
                for (int g = 0; g < 4; ++g)
                    LDSM_X4(vf[g][0], vf[g][1], vf[g][2], vf[g][3],
                            vstage + (uint32_t)(g * 16 + (lane & 15)) * 144 + coff);
                #pragma unroll
                for (int rg = 0; rg < 2; ++rg)
                    #pragma unroll
                    for (int g = 0; g < 4; ++g)
                        #pragma unroll
                        for (int p = 0; p < 2; ++p)
                            mma_f16(acc[rg][g * 2 + p], pa[rg][ks], vf[g][p], vf[g][p + 2]);
            }

            stc = (stc == 2) ? 0 : stc + 1;
        }

        // ---- epilogue: fp16 out ----
        uint32_t* o = reinterpret_cast<uint32_t*>(atout);
        #pragma unroll
        for (int rg = 0; rg < 2; ++rg) {
            float inv0 = 1.f / lrun[rg][0], inv1 = 1.f / lrun[rg][1];
            size_t r0o = (size_t)(b * S_ + rowg[rg][0]) * HID + h * HD;
            size_t r1o = (size_t)(b * S_ + rowg[rg][1]) * HID + h * HD;
            #pragma unroll
            for (int nt = 0; nt < 8; ++nt) {
                int d = nt * 8 + (lane & 3) * 2;
                o[(r0o + d) >> 1] = pack2h(acc[rg][nt][0] * inv0, acc[rg][nt][1] * inv0);
                o[(r1o + d) >> 1] = pack2h(acc[rg][nt][2] * inv1, acc[rg][nt][3] * inv1);
            }
        }
        __syncthreads();   // drain before Q/stage reuse in next half
    }
}

// ---------------------------------------------------------------------------
// kernel_launch
// ---------------------------------------------------------------------------
extern "C" void kernel_launch(void* const* d_in, const int* in_sizes, int n_in,
                              void* d_out, int out_size)
{
    const float* hs    = (const float*)d_in[0];
    const int*   amask = (const int*)  d_in[1];
    const float* Wq    = (const float*)d_in[2];
    const float* bq    = (const float*)d_in[3];
    const float* Wk    = (const float*)d_in[4];
    const float* bk    = (const float*)d_in[5];
    const float* Wv    = (const float*)d_in[6];
    const float* bv    = (const float*)d_in[7];
    const float* Wo    = (const float*)d_in[8];
    const float* bo    = (const float*)d_in[9];
    float* out = (float*)d_out;

    float* biasp;
    cudaGetSymbolAddress((void**)&biasp, g_bias);
    __half *hsp, *atp, *wcp, *wop;
    cudaGetSymbolAddress((void**)&hsp, g_hs);
    cudaGetSymbolAddress((void**)&atp, g_at);
    cudaGetSymbolAddress((void**)&wcp, g_Wc);
    cudaGetSymbolAddress((void**)&wop, g_Wo);

    cudaFuncSetAttribute(gemm_mma_kernel<0>,
                         cudaFuncAttributeMaxDynamicSharedMemorySize, GEMM_SMEM);
    cudaFuncSetAttribute(gemm_mma_kernel<1>,
                         cudaFuncAttributeMaxDynamicSharedMemorySize, GEMM_SMEM);
    cudaFuncSetAttribute(attn_mma_kernel,
                         cudaFuncAttributeMaxDynamicSharedMemorySize, ATTN_SMEM);

    const int M = B_ * S_;
    const int nhs = M * HID;

    prep_kernel<<<dim3(32, 32, 5), dim3(32, 8)>>>(Wq, Wk, Wv, Wo, bq, bk, bv);
    cvt_kernel<<<(nhs / 2 + 255) / 256, 256>>>(hs, hsp, nhs);

    // fused QKV projection + RoPE + fp16 Q/K + V transpose
    gemm_mma_kernel<1><<<dim3(NCAT / 128, M / 128), 256, GEMM_SMEM>>>(
        hsp, wcp, biasp, nullptr, NCAT, HID);

    // attention (128 threads, 4 warps x 32 rows)
    attn_mma_kernel<<<dim3(8, NH, B_), 128, ATTN_SMEM>>>(amask, atp);

    // output projection
    gemm_mma_kernel<0><<<dim3(HID / 128, M / 128), 256, GEMM_SMEM>>>(
        atp, wop, bo, out, HID, HID);
}

// round 15
// speedup vs baseline: 1.1441x; 1.1441x over previous
#include <cuda_runtime.h>
#include <cuda_fp16.h>
#include <cstdint>
#include <math.h>

#define B_    2
#define S_    2048
#define HID   1024
#define NH    16
#define NKV   4
#define HD    64
#define NCAT  1536            // 1024 (Q) + 256 (K) + 256 (V)

// ---------------------------------------------------------------------------
// Scratch (device globals)
// ---------------------------------------------------------------------------
__device__ float g_cos[S_ * 32];
__device__ float g_sin[S_ * 32];
__device__ float g_bias[NCAT];

__device__ __half g_hs[(size_t)B_ * S_ * HID];
__device__ __half g_at[(size_t)B_ * S_ * HID];
__device__ __half g_Wc[NCAT * HID];                  // [1536,1024] K-major rows
__device__ __half g_Wo[HID * HID];
__device__ __half g_Q[(size_t)B_ * S_ * HID];        // post-rope Q fp16 (pre-scaled)
__device__ __half g_K[(size_t)B_ * S_ * NKV * HD];   // post-rope K fp16
__device__ __half g_Vt[(size_t)B_ * NKV * HD * S_];  // [b,kvh,d,s] fp16

// ---------------------------------------------------------------------------
// helpers
// ---------------------------------------------------------------------------
__device__ __forceinline__ uint32_t smem_u32(const void* p) {
    uint32_t a;
    asm("{ .reg .u64 t; cvta.to.shared.u64 t, %1; cvt.u32.u64 %0, t; }" : "=r"(a) : "l"(p));
    return a;
}
#define LDSM_X4(r0, r1, r2, r3, addr) \
    asm volatile("ldmatrix.sync.aligned.m8n8.x4.shared.b16 {%0,%1,%2,%3}, [%4];" \
        : "=r"(r0), "=r"(r1), "=r"(r2), "=r"(r3) : "r"(addr))
#define CP_A16(dst, src) \
    asm volatile("cp.async.cg.shared.global [%0], [%1], 16;" :: "r"(dst), "l"(src))
#define CP_COMMIT() asm volatile("cp.async.commit_group;" ::: "memory")
#define CP_WAIT0()  asm volatile("cp.async.wait_group 0;" ::: "memory")
#define CP_WAIT1()  asm volatile("cp.async.wait_group 1;" ::: "memory")

__device__ __forceinline__ void mma_f16(float* d, const uint32_t* a,
                                        uint32_t b0, uint32_t b1) {
    asm volatile(
        "mma.sync.aligned.m16n8k16.row.col.f32.f16.f16.f32 "
        "{%0,%1,%2,%3}, {%4,%5,%6,%7}, {%8,%9}, {%0,%1,%2,%3};"
        : "+f"(d[0]), "+f"(d[1]), "+f"(d[2]), "+f"(d[3])
        : "r"(a[0]), "r"(a[1]), "r"(a[2]), "r"(a[3]), "r"(b0), "r"(b1));
}
__device__ __forceinline__ uint32_t pack2h(float x, float y) {
    __half2 h = __floats2half2_rn(x, y);
    return *reinterpret_cast<uint32_t*>(&h);
}
__device__ __forceinline__ float fexp2(float x) {
    float y;
    asm("ex2.approx.f32 %0, %1;" : "=f"(y) : "f"(x));
    return y;
}
__device__ __forceinline__ uint32_t hexp2x2(uint32_t x) {
    uint32_t y;
    asm("ex2.approx.f16x2 %0, %1;" : "=r"(y) : "r"(x));
    return y;
}

// ---------------------------------------------------------------------------
// Prep: z=0..3 weight transpose; z=4 rope table + bias; z=5..12 hs fp32->fp16.
// ---------------------------------------------------------------------------
__global__ void prep_kernel(const float* __restrict__ Wq,
                            const float* __restrict__ Wk,
                            const float* __restrict__ Wv,
                            const float* __restrict__ Wo,
                            const float* __restrict__ bq,
                            const float* __restrict__ bk,
                            const float* __restrict__ bv,
                            const float* __restrict__ hs,
                            __half* __restrict__ hsp) {
    int z = blockIdx.z;
    int tid = threadIdx.y * 32 + threadIdx.x;
    if (z >= 5) {
        // hs fp32 -> fp16: 8 planes x 262144 x 2 elements = 4.19M
        int idx = (blockIdx.y * 32 + blockIdx.x) * 256 + tid;
        int i = ((z - 5) * 262144 + idx) * 2;
        float2 v = *reinterpret_cast<const float2*>(hs + i);
        *reinterpret_cast<uint32_t*>(hsp + i) = pack2h(v.x, v.y);
        return;
    }
    if (z == 4) {
        int idx = (blockIdx.y * 32 + blockIdx.x) * 256 + tid;
        if (idx < NCAT)
            g_bias[idx] = (idx < 1024) ? bq[idx] : (idx < 1280) ? bk[idx - 1024] : bv[idx - 1280];
        if (idx >= S_ * 32) return;
        int t = idx >> 5, j = idx & 31;
        double inv = exp2(-(double)j * 0.5190512648261507);
        float ang = (float)((double)t * inv);
        float s, c;
        sincosf(ang, &s, &c);
        g_cos[idx] = c;
        g_sin[idx] = s;
        return;
    }

    __shared__ float t[32][33];
    const float* W;
    __half* dst;
    int N, rowoff;
    if (z == 0)      { W = Wq; N = HID; rowoff = 0;    dst = g_Wc; }
    else if (z == 1) { W = Wk; N = 256; rowoff = 1024; dst = g_Wc; }
    else if (z == 2) { W = Wv; N = 256; rowoff = 1280; dst = g_Wc; }
    else             { W = Wo; N = HID; rowoff = 0;    dst = g_Wo; }

    int n0 = blockIdx.x * 32, k0 = blockIdx.y * 32;
    if (n0 >= N) return;
    int x = threadIdx.x, y = threadIdx.y;
    #pragma unroll
    for (int yy = y; yy < 32; yy += 8)
        t[yy][x] = W[(size_t)(k0 + yy) * N + n0 + x];
    __syncthreads();
    #pragma unroll
    for (int yy = y; yy < 32; yy += 8)
        dst[(size_t)(rowoff + n0 + yy) * HID + k0 + x] = __float2half(t[x][yy]);
}

// ---------------------------------------------------------------------------
// GEMM fp16 mma.sync: BK=64 chunks, 3-stage ring, ONE sync per chunk.
// MODE 0: fp32 C + bias. MODE 1: fused RoPE (Q pre-scaled) + V transpose.
// ---------------------------------------------------------------------------
#define GEMM_SMEM (3 * 32768)

template <int MODE>
__global__ __launch_bounds__(256, 2) void gemm_mma_kernel(
    const __half* __restrict__ Ap, const __half* __restrict__ Wp,
    const float* __restrict__ bias, float* __restrict__ C, int ldc, int K)
{
    extern __shared__ char smx[];
    const int tid = threadIdx.x, lane = tid & 31, wid = tid >> 5;
    const int wm = wid & 1, wn = wid >> 1;
    const int m0 = blockIdx.y * 128, n0 = blockIdx.x * 128;
    const uint32_t sbase = smem_u32(smx);

    float acc[4][4][4];
    #pragma unroll
    for (int a = 0; a < 4; a++)
        #pragma unroll
        for (int bb = 0; bb < 4; bb++)
            #pragma unroll
            for (int c = 0; c < 4; c++) acc[a][bb][c] = 0.f;

    auto load_stage = [&](int ch, int st) {
        const uint32_t base = sbase + (uint32_t)st * 32768u;
        const int k0 = ch * 64;
        #pragma unroll
        for (int it = 0; it < 8; ++it) {
            int i = it * 256 + tid;
            int mat = i >> 10;
            int row = (i >> 3) & 127;
            int seg = i & 7;
            uint32_t dst = base + (uint32_t)mat * 16384u
                         + (uint32_t)(row * 128 + (((seg ^ (row & 7))) << 4));
            const __half* p = mat ? (Wp + (size_t)(n0 + row) * K)
                                  : (Ap + (size_t)(m0 + row) * K);
            CP_A16(dst, p + k0 + seg * 8);
        }
    };

    const int NCH = K / 64;
    load_stage(0, 0); CP_COMMIT();
    if (NCH > 1) { load_stage(1, 1); CP_COMMIT(); }

    int stc = 0;
    for (int ch = 0; ch < NCH; ++ch) {
        if (ch + 1 < NCH) CP_WAIT1(); else CP_WAIT0();
        __syncthreads();

        const uint32_t sA = sbase + (uint32_t)stc * 32768u;
        const uint32_t sW = sA + 16384u;

        #pragma unroll
        for (int ks = 0; ks < 4; ++ks) {
            const int colh = ks * 2 + (lane >> 4);
            uint32_t a[4][4], bfr[2][4];
            #pragma unroll
            for (int mi = 0; mi < 4; ++mi) {
                int row = wm * 64 + mi * 16 + (lane & 15);
                LDSM_X4(a[mi][0], a[mi][1], a[mi][2], a[mi][3],
                        sA + (uint32_t)(row * 128 + ((colh ^ (row & 7)) << 4)));
            }
            #pragma unroll
            for (int g = 0; g < 2; ++g) {
                int row = wn * 32 + g * 16 + (lane & 15);
                LDSM_X4(bfr[g][0], bfr[g][1], bfr[g][2], bfr[g][3],
                        sW + (uint32_t)(row * 128 + ((colh ^ (row & 7)) << 4)));
            }
            #pragma unroll
            for (int mi = 0; mi < 4; ++mi) {
                #pragma unroll
                for (int j = 0; j < 4; ++j) {
                    const int g = j >> 1, p = j & 1;
                    mma_f16(acc[mi][j], a[mi], bfr[g][p], bfr[g][p + 2]);
                }
            }
            if (ks == 0 && ch + 2 < NCH) { load_stage(ch + 2, (stc + 2) % 3); CP_COMMIT(); }
        }
        stc = (stc == 2) ? 0 : stc + 1;
    }

    // epilogue
    const float SC2 = 0.125f * 1.44269504f;    // folded into Q only
    #pragma unroll
    for (int mi = 0; mi < 4; ++mi) {
        const int r = m0 + wm * 64 + mi * 16 + (lane >> 2);
        #pragma unroll
        for (int j = 0; j < 4; ++j) {
            const int col = n0 + wn * 32 + j * 8 + (lane & 3) * 2;
            const float b0 = bias[col], b1 = bias[col + 1];
            float x0 = acc[mi][j][0] + b0, x1 = acc[mi][j][1] + b1;
            float x2 = acc[mi][j][2] + b0, x3 = acc[mi][j][3] + b1;
            if (MODE == 0) {
                *reinterpret_cast<float2*>(C + (size_t)r * ldc + col) = make_float2(x0, x1);
                *reinterpret_cast<float2*>(C + (size_t)(r + 8) * ldc + col) = make_float2(x2, x3);
            } else {
                if (col < 1280) {
                    const int pos0 = r & (S_ - 1), pos1 = (r + 8) & (S_ - 1);
                    const int j0 = col & 31;
                    float2 cc0 = *reinterpret_cast<const float2*>(&g_cos[pos0 * 32 + j0]);
                    float2 ss0 = *reinterpret_cast<const float2*>(&g_sin[pos0 * 32 + j0]);
                    float2 cc1 = *reinterpret_cast<const float2*>(&g_cos[pos1 * 32 + j0]);
                    float2 ss1 = *reinterpret_cast<const float2*>(&g_sin[pos1 * 32 + j0]);
                    float y0 = x0 * cc0.x - x1 * ss0.x;
                    float y1 = x1 * cc0.y + x0 * ss0.y;
                    float y2 = x2 * cc1.x - x3 * ss1.x;
                    float y3 = x3 * cc1.y + x2 * ss1.y;
                    if (col < 1024) {
                        y0 *= SC2; y1 *= SC2; y2 *= SC2; y3 *= SC2;
                        uint32_t* o = reinterpret_cast<uint32_t*>(g_Q);
                        o[(size_t)r * 512 + (col >> 1)]       = pack2h(y0, y1);
                        o[(size_t)(r + 8) * 512 + (col >> 1)] = pack2h(y2, y3);
                    } else {
                        uint32_t* o = reinterpret_cast<uint32_t*>(g_K);
                        o[(size_t)r * 128 + ((col - 1024) >> 1)]       = pack2h(y0, y1);
                        o[(size_t)(r + 8) * 128 + ((col - 1024) >> 1)] = pack2h(y2, y3);
                    }
                } else {
                    // fused V transpose: fp16 to g_Vt[b][kvh][d][s]
                    const int d = col - 1280;
                    const int kvh = d >> 6, dd = d & 63;
                    const int bb2 = r >> 11, s = r & (S_ - 1);
                    __half* vt = g_Vt + ((size_t)(bb2 * NKV + kvh) * HD + dd) * S_;
                    vt[s]           = __float2half(x0);
                    vt[S_ + s]      = __float2half(x1);
                    vt[s + 8]       = __float2half(x2);
                    vt[S_ + s + 8]  = __float2half(x3);
                }
            }
        }
    }
}

// ---------------------------------------------------------------------------
// Flash attention fp16 (R13 shape): 8 warps x 16 rows, 256 threads,
// load-balanced pairs {15-p, p}, 3-stage K/V ring, ONE sync per tile,
// ex2.f16x2 softmax, ones-MMA row sums, warp-ballot skip-rescale.
// ---------------------------------------------------------------------------
#define AQ_OFF  0                                  // 128 x 144 = 18432
#define AST_OFF 18432                              // 3 stages x (K 9216 + V 9216)
#define AOK_OFF (AST_OFF + 3 * 18432)              // 32 tile-ok flags
#define AAM_OFF (AOK_OFF + 128)                    // mask 8192
#define ATTN_SMEM (AAM_OFF + S_ * 4)

__global__ __launch_bounds__(256, 2) void attn_mma_kernel(
    const int* __restrict__ amask, __half* __restrict__ atout)
{
    extern __shared__ char sm[];
    const uint32_t sb = smem_u32(sm);
    int* am  = reinterpret_cast<int*>(sm + AAM_OFF);
    int* amok = reinterpret_cast<int*>(sm + AOK_OFF);

    const int tid = threadIdx.x, lane = tid & 31, w = tid >> 5;
    const int pr = blockIdx.x, h = blockIdx.y, b = blockIdx.z;
    const int kvh = h >> 2;
    const uint32_t ONES = 0x3C003C00u;

    #pragma unroll
    for (int it = 0; it < 8; ++it)
        am[it * 256 + tid] = amask[b * S_ + it * 256 + tid];
    __syncthreads();
    if (tid < 32) {
        int ok = 1;
        for (int j = 0; j < 64; ++j) ok &= (am[tid * 64 + j] != 0);
        amok[tid] = ok;
    }

    auto prefetch_kv = [&](int kt, int st) {
        const int k0 = kt * 64;
        const uint32_t base = sb + AST_OFF + (uint32_t)st * 18432u;
        const __half* kp = g_K + (size_t)(b * S_ + k0) * (NKV * HD) + kvh * HD;
        const __half* vp = g_Vt + ((size_t)(b * NKV + kvh) * HD) * S_ + k0;
        #pragma unroll
        for (int it = 0; it < 4; ++it) {
            int i = it * 256 + tid;
            int mat = i >> 9;
            int row = (i >> 3) & 63;
            int seg = i & 7;
            uint32_t dst = base + (uint32_t)mat * 9216u + (uint32_t)(row * 144 + seg * 16);
            const __half* p = mat ? (vp + (size_t)row * S_) : (kp + (size_t)row * (NKV * HD));
            CP_A16(dst, p + seg * 8);
        }
    };

    for (int half = 0; half < 2; ++half) {
        const int qb = half ? pr : (15 - pr);      // long block first
        const int q0 = qb * 128;
        const int nkt = 2 * qb + 2;                // >= 2

        {
            const __half* qp = g_Q + (size_t)(b * S_ + q0) * HID + h * HD;
            #pragma unroll
            for (int it = 0; it < 4; ++it) {
                int i = it * 256 + tid;
                int row = i >> 3, seg = i & 7;
                CP_A16(sb + AQ_OFF + (uint32_t)(row * 144 + seg * 16),
                       qp + (size_t)row * HID + seg * 8);
            }
        }
        prefetch_kv(0, 0); CP_COMMIT();            // group0 = Q + kv0
        prefetch_kv(1, 1); CP_COMMIT();            // group1 = kv1

        CP_WAIT1();
        __syncthreads();

        uint32_t qf[4][4];
        {
            uint32_t rb = sb + AQ_OFF + (uint32_t)(w * 16 + (lane & 15)) * 144;
            #pragma unroll
            for (int ks = 0; ks < 4; ++ks)
                LDSM_X4(qf[ks][0], qf[ks][1], qf[ks][2], qf[ks][3],
                        rb + (uint32_t)(ks * 32 + ((lane >> 4) << 4)));
        }

        float acc[8][4];
        #pragma unroll
        for (int nt = 0; nt < 8; ++nt)
            #pragma unroll
            for (int c = 0; c < 4; ++c) acc[nt][c] = 0.f;
        float m0 = -1e30f, m1 = -1e30f, l0 = 0.f, l1 = 0.f;
        const int row0g = q0 + w * 16 + (lane >> 2);
        const int row1g = row0g + 8;

        int stc = 0;
        for (int kt = 0; kt < nkt; ++kt) {
            if (kt > 0) {
                if (kt + 1 < nkt) CP_WAIT1(); else CP_WAIT0();
                __syncthreads();
            }
            if (kt + 2 < nkt) { prefetch_kv(kt + 2, (stc + 2) % 3); CP_COMMIT(); }

            const int k0 = kt * 64;
            const uint32_t stage = sb + AST_OFF + (uint32_t)stc * 18432u;

            float s[8][4];
            #pragma unroll
            for (int nt = 0; nt < 8; ++nt)
                #pragma unroll
                for (int c = 0; c < 4; ++c) s[nt][c] = 0.f;

            #pragma unroll
            for (int ks = 0; ks < 4; ++ks) {
                const uint32_t coff = (uint32_t)(ks * 32 + ((lane >> 4) << 4));
                uint32_t kf[4][4];
                #pragma unroll
                for (int g = 0; g < 4; ++g)
                    LDSM_X4(kf[g][0], kf[g][1], kf[g][2], kf[g][3],
                            stage + (uint32_t)(g * 16 + (lane & 15)) * 144 + coff);
                #pragma unroll
                for (int g = 0; g < 4; ++g)
                    #pragma unroll
                    for (int p = 0; p < 2; ++p)
                        mma_f16(s[g * 2 + p], qf[ks], kf[g][p], kf[g][p + 2]);
            }

            const bool fast = (k0 + 63 <= q0 + w * 16) && amok[k0 >> 6];
            if (!fast) {
                #pragma unroll
                for (int nt = 0; nt < 8; ++nt) {
                    int cl = nt * 8 + (lane & 3) * 2;
                    int cg0 = k0 + cl, cg1 = cg0 + 1;
                    bool ok0 = am[cg0] != 0, ok1 = am[cg1] != 0;
                    if (!(ok0 && cg0 <= row0g)) s[nt][0] = -1e30f;
                    if (!(ok1 && cg1 <= row0g)) s[nt][1] = -1e30f;
                    if (!(ok0 && cg0 <= row1g)) s[nt][2] = -1e30f;
                    if (!(ok1 && cg1 <= row1g)) s[nt][3] = -1e30f;
                }
            }

            float mt0 = -1e30f, mt1 = -1e30f;
            #pragma unroll
            for (int nt = 0; nt < 8; ++nt) {
                mt0 = fmaxf(mt0, fmaxf(s[nt][0], s[nt][1]));
                mt1 = fmaxf(mt1, fmaxf(s[nt][2], s[nt][3]));
            }
            mt0 = fmaxf(mt0, __shfl_xor_sync(0xffffffffu, mt0, 1));
            mt0 = fmaxf(mt0, __shfl_xor_sync(0xffffffffu, mt0, 2));
            mt1 = fmaxf(mt1, __shfl_xor_sync(0xffffffffu, mt1, 1));
            mt1 = fmaxf(mt1, __shfl_xor_sync(0xffffffffu, mt1, 2));

            float mn0 = fmaxf(m0, mt0), mn1 = fmaxf(m1, mt1);
            bool changed = (mn0 > m0) || (mn1 > m1);

            uint32_t pa[4][4];
            #pragma unroll
            for (int nt = 0; nt < 8; ++nt) {
                int t = nt >> 1, q = nt & 1;
                pa[t][q * 2 + 0] = hexp2x2(pack2h(s[nt][0] - mn0, s[nt][1] - mn0));
                pa[t][q * 2 + 1] = hexp2x2(pack2h(s[nt][2] - mn1, s[nt][3] - mn1));
            }
            float sum4[4] = {0.f, 0.f, 0.f, 0.f};
            #pragma unroll
            for (int ks = 0; ks < 4; ++ks)
                mma_f16(sum4, pa[ks], ONES, ONES);

            // rescale only when some row max changed anywhere in the warp
            if (__ballot_sync(0xffffffffu, changed)) {
                float corr0 = fexp2(m0 - mn0), corr1 = fexp2(m1 - mn1);
                l0 = l0 * corr0 + sum4[0];
                l1 = l1 * corr1 + sum4[2];
                m0 = mn0; m1 = mn1;
                #pragma unroll
                for (int nt = 0; nt < 8; ++nt) {
                    acc[nt][0] *= corr0; acc[nt][1] *= corr0;
                    acc[nt][2] *= corr1; acc[nt][3] *= corr1;
                }
            } else {
                l0 += sum4[0];
                l1 += sum4[2];
            }

            const uint32_t vstage = stage + 9216u;
            #pragma unroll
            for (int ks = 0; ks < 4; ++ks) {
                const uint32_t coff = (uint32_t)(ks * 32 + ((lane >> 4) << 4));
                uint32_t vf[4][4];
                #pragma unroll
                for (int g = 0; g < 4; ++g)
                    LDSM_X4(vf[g][0], vf[g][1], vf[g][2], vf[g][3],
                            vstage + (uint32_t)(g * 16 + (lane & 15)) * 144 + coff);
                #pragma unroll
                for (int g = 0; g < 4; ++g)
                    #pragma unroll
                    for (int p = 0; p < 2; ++p)
                        mma_f16(acc[g * 2 + p], pa[ks], vf[g][p], vf[g][p + 2]);
            }

            stc = (stc == 2) ? 0 : stc + 1;
        }

        float inv0 = 1.f / l0, inv1 = 1.f / l1;
        size_t r0o = (size_t)(b * S_ + row0g) * HID + h * HD;
        size_t r1o = r0o + (size_t)8 * HID;
        uint32_t* o = reinterpret_cast<uint32_t*>(atout);
        #pragma unroll
        for (int nt = 0; nt < 8; ++nt) {
            int d = nt * 8 + (lane & 3) * 2;
            o[(r0o + d) >> 1] = pack2h(acc[nt][0] * inv0, acc[nt][1] * inv0);
            o[(r1o + d) >> 1] = pack2h(acc[nt][2] * inv1, acc[nt][3] * inv1);
        }
        __syncthreads();
    }
}

// ---------------------------------------------------------------------------
// kernel_launch
// ---------------------------------------------------------------------------
extern "C" void kernel_launch(void* const* d_in, const int* in_sizes, int n_in,
                              void* d_out, int out_size)
{
    const float* hs    = (const float*)d_in[0];
    const int*   amask = (const int*)  d_in[1];
    const float* Wq    = (const float*)d_in[2];
    const float* bq    = (const float*)d_in[3];
    const float* Wk    = (const float*)d_in[4];
    const float* bk    = (const float*)d_in[5];
    const float* Wv    = (const float*)d_in[6];
    const float* bv    = (const float*)d_in[7];
    const float* Wo    = (const float*)d_in[8];
    const float* bo    = (const float*)d_in[9];
    float* out = (float*)d_out;

    float* biasp;
    cudaGetSymbolAddress((void**)&biasp, g_bias);
    __half *hsp, *atp, *wcp, *wop;
    cudaGetSymbolAddress((void**)&hsp, g_hs);
    cudaGetSymbolAddress((void**)&atp, g_at);
    cudaGetSymbolAddress((void**)&wcp, g_Wc);
    cudaGetSymbolAddress((void**)&wop, g_Wo);

    cudaFuncSetAttribute(gemm_mma_kernel<0>,
                         cudaFuncAttributeMaxDynamicSharedMemorySize, GEMM_SMEM);
    cudaFuncSetAttribute(gemm_mma_kernel<1>,
                         cudaFuncAttributeMaxDynamicSharedMemorySize, GEMM_SMEM);
    cudaFuncSetAttribute(attn_mma_kernel,
                         cudaFuncAttributeMaxDynamicSharedMemorySize, ATTN_SMEM);

    const int M = B_ * S_;

    // prep: weights z=0..3, rope+bias z=4, hs conversion z=5..12
    prep_kernel<<<dim3(32, 32, 13), dim3(32, 8)>>>(Wq, Wk, Wv, Wo, bq, bk, bv, hs, hsp);

    // fused QKV projection + RoPE + fp16 Q/K + V transpose
    gemm_mma_kernel<1><<<dim3(NCAT / 128, M / 128), 256, GEMM_SMEM>>>(
        hsp, wcp, biasp, nullptr, NCAT, HID);

    // attention (256 threads, 8 warps x 16 rows — R13 shape + skip-rescale)
    attn_mma_kernel<<<dim3(8, NH, B_), 256, ATTN_SMEM>>>(amask, atp);

    // output projection
    gemm_mma_kernel<0><<<dim3(HID / 128, M / 128), 256, GEMM_SMEM>>>(
        atp, wop, bo, out, HID, HID);
}